// round 4
// baseline (speedup 1.0000x reference)
#include <cuda_runtime.h>
#include <cuda_bf16.h>

#define BATCH 2
#define SEQ   2048
#define DM    1024
#define NH    16
#define DH    64
#define KS    32

#define MROWS (BATCH*SEQ)   // 4096
#define FULLM 0xffffffffu
#define NTILE 16
#define NTRI  136

// ---------------- scratch ----------------------------------------------------
__device__ float g_Q [BATCH*SEQ*DM];
__device__ float g_K [BATCH*SEQ*DM];
__device__ float g_V [BATCH*SEQ*DM];
__device__ float g_HO[BATCH*SEQ*DM];
__device__ float g_WGT[BATCH*NH*SEQ*KS];
__device__ int   g_IDX[BATCH*NH*SEQ*KS];
__device__ float g_SC[(size_t)BATCH*NH*SEQ*SEQ];

__device__ __forceinline__ float neg_inf() { return __int_as_float(0xff800000); }

// ---------------- packed fp32x2 helpers (B300 FFMA2) -------------------------
typedef unsigned long long u64;

__device__ __forceinline__ u64 pack2(float x, float y) {
    u64 r; asm("mov.b64 %0, {%1,%2};" : "=l"(r) : "f"(x), "f"(y)); return r;
}
__device__ __forceinline__ u64 dup2(float x) {
    u64 r; asm("mov.b64 %0, {%1,%1};" : "=l"(r) : "f"(x)); return r;
}
__device__ __forceinline__ void fma2(u64& d, u64 a, u64 b) {
    asm("fma.rn.f32x2 %0, %1, %2, %0;" : "+l"(d) : "l"(a), "l"(b));
}
__device__ __forceinline__ float2 unpack2(u64 v) {
    float2 f; asm("mov.b64 {%0,%1}, %2;" : "=f"(f.x), "=f"(f.y) : "l"(v)); return f;
}

// ---------------- GEMM: C[M,N] = A[M,K] @ W[N,K]^T + bias --------------------
#define BM 128
#define BN 128
#define BK 8

__global__ __launch_bounds__(256) void gemm_kernel(
    const float* __restrict__ A, const float* __restrict__ W,
    const float* __restrict__ bias, float* __restrict__ C,
    int M, int N, int K)
{
    __shared__ float As[BK][BM];
    __shared__ float Ws[BK][BN];
    int tid = threadIdx.x;
    int tx = tid & 15, ty = tid >> 4;
    int bm = blockIdx.y * BM, bn = blockIdx.x * BN;

    u64 acc[8][4];                       // pairs along j
#pragma unroll
    for (int i = 0; i < 8; i++)
#pragma unroll
        for (int j = 0; j < 4; j++) acc[i][j] = 0ull;

    int lr = tid >> 1;
    int lc = (tid & 1) * 4;

    for (int k0 = 0; k0 < K; k0 += BK) {
        float4 av = *(const float4*)(A + (size_t)(bm + lr) * K + k0 + lc);
        float4 wv = *(const float4*)(W + (size_t)(bn + lr) * K + k0 + lc);
        As[lc+0][lr] = av.x; As[lc+1][lr] = av.y; As[lc+2][lr] = av.z; As[lc+3][lr] = av.w;
        Ws[lc+0][lr] = wv.x; Ws[lc+1][lr] = wv.y; Ws[lc+2][lr] = wv.z; Ws[lc+3][lr] = wv.w;
        __syncthreads();
#pragma unroll
        for (int kk = 0; kk < BK; kk++) {
            float4 a0 = *(const float4*)&As[kk][ty*4];
            float4 a1 = *(const float4*)&As[kk][64 + ty*4];
            float4 w0 = *(const float4*)&Ws[kk][tx*4];
            float4 w1 = *(const float4*)&Ws[kk][64 + tx*4];
            u64 wp[4] = { pack2(w0.x,w0.y), pack2(w0.z,w0.w),
                          pack2(w1.x,w1.y), pack2(w1.z,w1.w) };
            float a[8] = {a0.x,a0.y,a0.z,a0.w,a1.x,a1.y,a1.z,a1.w};
#pragma unroll
            for (int i = 0; i < 8; i++) {
                u64 ai = dup2(a[i]);
#pragma unroll
                for (int j = 0; j < 4; j++)
                    fma2(acc[i][j], ai, wp[j]);
            }
        }
        __syncthreads();
    }

    float4 b0 = *(const float4*)(bias + bn + tx*4);
    float4 b1 = *(const float4*)(bias + bn + 64 + tx*4);
    float bb[8] = {b0.x,b0.y,b0.z,b0.w,b1.x,b1.y,b1.z,b1.w};

#pragma unroll
    for (int i = 0; i < 8; i++) {
        int m = bm + ((i < 4) ? (ty*4 + i) : (64 + ty*4 + i - 4));
        float2 p0 = unpack2(acc[i][0]), p1 = unpack2(acc[i][1]);
        float2 p2 = unpack2(acc[i][2]), p3 = unpack2(acc[i][3]);
        float4 o0 = make_float4(p0.x+bb[0], p0.y+bb[1], p1.x+bb[2], p1.y+bb[3]);
        float4 o1 = make_float4(p2.x+bb[4], p2.y+bb[5], p3.x+bb[6], p3.y+bb[7]);
        *(float4*)(C + (size_t)m * N + bn + tx*4)      = o0;
        *(float4*)(C + (size_t)m * N + bn + 64 + tx*4) = o1;
    }
}

// ---------------- score GEMM: S[q,k] = (Q_row_q . K_row_k) / 8 ---------------
__global__ __launch_bounds__(256) void score_kernel(
    const float* __restrict__ Q, const float* __restrict__ Kg,
    float* __restrict__ SC)
{
    __shared__ float As[16][BM];
    __shared__ float Ws[16][BN];

    const int t = blockIdx.x;
    const int h = blockIdx.y, b = blockIdx.z;
    int qt = (int)((sqrtf(8.f * t + 1.f) - 1.f) * 0.5f);
    while ((qt + 1) * (qt + 2) / 2 <= t) qt++;
    while (qt * (qt + 1) / 2 > t) qt--;
    int kt = t - qt * (qt + 1) / 2;

    const int tid = threadIdx.x;
    const int tx = tid & 15, ty = tid >> 4;
    const int bm = qt * BM, bn = kt * BN;

    u64 acc[8][4];
#pragma unroll
    for (int i = 0; i < 8; i++)
#pragma unroll
        for (int j = 0; j < 4; j++) acc[i][j] = 0ull;

    const float* Qb = Q  + (size_t)b*SEQ*DM + h*DH;
    const float* Kb = Kg + (size_t)b*SEQ*DM + h*DH;

    int lr = tid >> 1;
    int lc = (tid & 1) * 8;

    for (int k0 = 0; k0 < DH; k0 += 16) {
        float4 a0 = *(const float4*)(Qb + (size_t)(bm + lr) * DM + k0 + lc);
        float4 a1 = *(const float4*)(Qb + (size_t)(bm + lr) * DM + k0 + lc + 4);
        float4 w0 = *(const float4*)(Kb + (size_t)(bn + lr) * DM + k0 + lc);
        float4 w1 = *(const float4*)(Kb + (size_t)(bn + lr) * DM + k0 + lc + 4);
        As[lc+0][lr]=a0.x; As[lc+1][lr]=a0.y; As[lc+2][lr]=a0.z; As[lc+3][lr]=a0.w;
        As[lc+4][lr]=a1.x; As[lc+5][lr]=a1.y; As[lc+6][lr]=a1.z; As[lc+7][lr]=a1.w;
        Ws[lc+0][lr]=w0.x; Ws[lc+1][lr]=w0.y; Ws[lc+2][lr]=w0.z; Ws[lc+3][lr]=w0.w;
        Ws[lc+4][lr]=w1.x; Ws[lc+5][lr]=w1.y; Ws[lc+6][lr]=w1.z; Ws[lc+7][lr]=w1.w;
        __syncthreads();
#pragma unroll
        for (int kk = 0; kk < 16; kk++) {
            float4 q0 = *(const float4*)&As[kk][ty*4];
            float4 q1 = *(const float4*)&As[kk][64 + ty*4];
            float4 k0v = *(const float4*)&Ws[kk][tx*4];
            float4 k1v = *(const float4*)&Ws[kk][64 + tx*4];
            u64 wp[4] = { pack2(k0v.x,k0v.y), pack2(k0v.z,k0v.w),
                          pack2(k1v.x,k1v.y), pack2(k1v.z,k1v.w) };
            float a[8] = {q0.x,q0.y,q0.z,q0.w,q1.x,q1.y,q1.z,q1.w};
#pragma unroll
            for (int i = 0; i < 8; i++) {
                u64 ai = dup2(a[i]);
#pragma unroll
                for (int j = 0; j < 4; j++)
                    fma2(acc[i][j], ai, wp[j]);
            }
        }
        __syncthreads();
    }

    float* Sb = SC + (((size_t)b*NH + h)*SEQ) * SEQ;
#pragma unroll
    for (int i = 0; i < 8; i++) {
        int m = bm + ((i < 4) ? (ty*4 + i) : (64 + ty*4 + i - 4));
        float2 p0 = unpack2(acc[i][0]), p1 = unpack2(acc[i][1]);
        float2 p2 = unpack2(acc[i][2]), p3 = unpack2(acc[i][3]);
        float4 o0 = make_float4(p0.x*.125f, p0.y*.125f, p1.x*.125f, p1.y*.125f);
        float4 o1 = make_float4(p2.x*.125f, p2.y*.125f, p3.x*.125f, p3.y*.125f);
        *(float4*)(Sb + (size_t)m * SEQ + bn + tx*4)      = o0;
        *(float4*)(Sb + (size_t)m * SEQ + bn + 64 + tx*4) = o1;
    }
}

// ---------------- selection: streaming top-32 + softmax + AV -----------------
__global__ __launch_bounds__(256) void select_kernel(
    const float* __restrict__ SC, const float* __restrict__ Vg,
    float* __restrict__ HO, float* __restrict__ WGT, int* __restrict__ IDX)
{
    const int h = blockIdx.y, b = blockIdx.z;
    const int tid = threadIdx.x;
    const int lane = tid & 31, wid = tid >> 5;
    const int q = blockIdx.x * 8 + wid;
    const float NEG = neg_inf();

    const float* row = SC + ((((size_t)b*NH + h)*SEQ) + q) * SEQ;

    float sv = NEG;
    int   si = 0x7fffffff;

    const int nb = (q + 32) >> 5;
    for (int bi = 0; bi < nb; bi++) {
        int k = (bi << 5) + lane;
        float v = NEG; int ii = 0x7fffffff;
        if (k <= q) { v = row[k]; ii = k; }

        float minv = __shfl_sync(FULLM, sv, 31);
        int   mini = __shfl_sync(FULLM, si, 31);
        bool contend = (v > minv) || (v == minv && v != NEG && ii < mini);
        unsigned m = __ballot_sync(FULLM, contend);
        while (m) {
            int src = __ffs(m) - 1; m &= m - 1;
            float nv = __shfl_sync(FULLM, v,  src);
            int   ni = __shfl_sync(FULLM, ii, src);
            bool better = (sv > nv) || (sv == nv && si < ni);
            unsigned bm2 = __ballot_sync(FULLM, better);
            int p = __popc(bm2);
            float upv = __shfl_up_sync(FULLM, sv, 1);
            int   upi = __shfl_up_sync(FULLM, si, 1);
            if (lane == p)      { sv = nv;  si = ni;  }
            else if (lane > p)  { sv = upv; si = upi; }
        }
    }

    bool valid = (sv != NEG);
    float mx = __shfl_sync(FULLM, sv, 0);
    float e = valid ? expf(sv - mx) : 0.f;
    float tot = e;
#pragma unroll
    for (int o = 16; o; o >>= 1) tot += __shfl_xor_sync(FULLM, tot, o);
    float w = e / tot;
    int iw = valid ? si : -1;

    size_t off = ((((size_t)b*NH + h)*SEQ) + (size_t)q) * KS + lane;
    WGT[off] = w;
    IDX[off] = iw;

    const float* Vb = Vg + (size_t)b*SEQ*DM + h*DH;
    float acc0 = 0.f, acc1 = 0.f;
#pragma unroll
    for (int j = 0; j < KS; j++) {
        float wj = __shfl_sync(FULLM, w, j);
        int   ij = __shfl_sync(FULLM, iw, j);
        if (ij >= 0) {
            const float* vr = Vb + (size_t)ij * DM;
            acc0 += wj * vr[lane];
            acc1 += wj * vr[lane + 32];
        }
    }
    float* out = HO + ((size_t)(b*SEQ + q)) * DM + h*DH;
    out[lane]      = acc0;
    out[lane + 32] = acc1;
}

// ---------------- mean over heads -> dense [B, SEQ, SEQ] ---------------------
__global__ __launch_bounds__(256) void mean_kernel(
    const float* __restrict__ WGT, const int* __restrict__ IDX,
    float* __restrict__ out_attn)
{
    __shared__ float row[SEQ];
    const int q = blockIdx.x, b = blockIdx.y;
    const int tid = threadIdx.x;
    for (int i = tid; i < SEQ; i += 256) row[i] = 0.f;
    __syncthreads();
    for (int h = 0; h < NH; h++) {
        if (tid < KS) {
            size_t off = ((((size_t)b*NH + h)*SEQ) + q) * KS + tid;
            float w = WGT[off];
            int k = IDX[off];
            if (k >= 0 && w > 0.f) row[k] += w * (1.0f / NH);
        }
        __syncthreads();
    }
    float* o = out_attn + ((size_t)b*SEQ + q) * SEQ;
    for (int i = tid; i < SEQ; i += 256) o[i] = row[i];
}

// ---------------- launch -----------------------------------------------------
extern "C" void kernel_launch(void* const* d_in, const int* in_sizes, int n_in,
                              void* d_out, int out_size)
{
    const float* x  = (const float*)d_in[0];
    const float* Wq = (const float*)d_in[1];
    const float* bq = (const float*)d_in[2];
    const float* Wk = (const float*)d_in[3];
    const float* bk = (const float*)d_in[4];
    const float* Wv = (const float*)d_in[5];
    const float* bv = (const float*)d_in[6];
    const float* Wo = (const float*)d_in[7];
    const float* bo = (const float*)d_in[8];

    float *Qp, *Kp, *Vp, *HOp, *Wp, *Sp; int* Ip;
    cudaGetSymbolAddress((void**)&Qp,  g_Q);
    cudaGetSymbolAddress((void**)&Kp,  g_K);
    cudaGetSymbolAddress((void**)&Vp,  g_V);
    cudaGetSymbolAddress((void**)&HOp, g_HO);
    cudaGetSymbolAddress((void**)&Wp,  g_WGT);
    cudaGetSymbolAddress((void**)&Ip,  g_IDX);
    cudaGetSymbolAddress((void**)&Sp,  g_SC);

    dim3 ggrid(DM / BN, MROWS / BM);   // (8, 32)

    gemm_kernel<<<ggrid, 256>>>(x, Wq, bq, Qp, MROWS, DM, DM);
    gemm_kernel<<<ggrid, 256>>>(x, Wk, bk, Kp, MROWS, DM, DM);
    gemm_kernel<<<ggrid, 256>>>(x, Wv, bv, Vp, MROWS, DM, DM);

    score_kernel<<<dim3(NTRI, NH, BATCH), 256>>>(Qp, Kp, Sp);
    select_kernel<<<dim3(SEQ / 8, NH, BATCH), 256>>>(Sp, Vp, HOp, Wp, Ip);

    float* yout = (float*)d_out;
    gemm_kernel<<<ggrid, 256>>>(HOp, Wo, bo, yout, MROWS, DM, DM);

    size_t ysz = (size_t)BATCH * SEQ * DM;
    size_t asz = (size_t)BATCH * SEQ * SEQ;
    if ((size_t)out_size >= ysz + asz) {
        mean_kernel<<<dim3(SEQ, BATCH), 256>>>(Wp, Ip, (float*)d_out + ysz);
    }
}